// round 1
// baseline (speedup 1.0000x reference)
#include <cuda_runtime.h>
#include <cuda_bf16.h>
#include <cstdint>

// Problem dims (fixed by the dataset)
#define MROWS 4096   // B*S = 2*2048
#define NDIM  4096   // n (input features)
#define MDIM  4096   // m (output features)
#define NIDX  (MDIM * (NDIM / 8))   // Qidxs elements = 4096*512

// Scratch: __device__ globals (allocation-free rule)
__device__ float g_X[(size_t)MROWS * NDIM];   // 64 MB: FWHT(input*SU)
__device__ float g_W[(size_t)MDIM * NDIM];    // 64 MB: dequantized W

// ---------------------------------------------------------------------------
// Kernel 1: dequantize W = grid[Qidxs] -> [m, n] row-major
// ---------------------------------------------------------------------------
__global__ void k_dequant(const float* __restrict__ grid,
                          const int*   __restrict__ qidxs)
{
    int t = blockIdx.x * blockDim.x + threadIdx.x;   // one per codeword
    if (t >= NIDX) return;
    int idx = qidxs[t];
    const float4* g = (const float4*)(grid + (size_t)idx * 8);
    float4* w = (float4*)(g_W + (size_t)t * 8);
    float4 a = g[0], b = g[1];
    w[0] = a; w[1] = b;
}

// ---------------------------------------------------------------------------
// Kernel 2: X = fwht(input * SU) row-wise, normalized by 1/64
// one block per row, 1024 threads, 16KB smem
// ---------------------------------------------------------------------------
__global__ void k_fwht_in(const float* __restrict__ in,
                          const float* __restrict__ SU)
{
    __shared__ float s[NDIM];
    const int row = blockIdx.x;
    const float* r = in + (size_t)row * NDIM;
    for (int i = threadIdx.x; i < NDIM; i += 1024)
        s[i] = r[i] * SU[i];
    __syncthreads();
    for (int h = 1; h < NDIM; h <<= 1) {
        for (int p = threadIdx.x; p < NDIM / 2; p += 1024) {
            int i = ((p & ~(h - 1)) << 1) | (p & (h - 1));
            int j = i + h;
            float a = s[i], b = s[j];
            s[i] = a + b;
            s[j] = a - b;
        }
        __syncthreads();
    }
    float* o = g_X + (size_t)row * NDIM;
    for (int i = threadIdx.x; i < NDIM; i += 1024)
        o[i] = s[i] * 0.015625f;   // 1/sqrt(4096)
}

// ---------------------------------------------------------------------------
// Kernel 3: SGEMM  C[M,N] = X[M,K] * W[N,K]^T   (both K-major -> NT gemm)
// 128x128 tile, BK=8, 256 threads, 8x8 per-thread micro-tile
// ---------------------------------------------------------------------------
#define BM 128
#define BN 128
#define BK 8
#define TM 8
#define TN 8

__global__ __launch_bounds__(256)
void k_sgemm_nt(float* __restrict__ C)
{
    __shared__ float As[BK][BM];
    __shared__ float Bs[BK][BN];

    const int tid = threadIdx.x;          // 0..255
    const int tx = tid & 15;              // 0..15
    const int ty = tid >> 4;              // 0..15
    const int bx = blockIdx.x;            // N tile
    const int by = blockIdx.y;            // M tile

    const float* Ab = g_X + (size_t)by * BM * NDIM;
    const float* Bb = g_W + (size_t)bx * BN * NDIM;

    const int lr = tid >> 1;              // 0..127 (row within tile)
    const int lc = (tid & 1) * 4;         // 0 or 4 (k offset)

    float acc[TM][TN];
    #pragma unroll
    for (int i = 0; i < TM; i++)
        #pragma unroll
        for (int j = 0; j < TN; j++) acc[i][j] = 0.f;

    for (int k0 = 0; k0 < NDIM; k0 += BK) {
        float4 a4 = *(const float4*)(Ab + (size_t)lr * NDIM + k0 + lc);
        float4 b4 = *(const float4*)(Bb + (size_t)lr * NDIM + k0 + lc);
        As[lc + 0][lr] = a4.x; As[lc + 1][lr] = a4.y;
        As[lc + 2][lr] = a4.z; As[lc + 3][lr] = a4.w;
        Bs[lc + 0][lr] = b4.x; Bs[lc + 1][lr] = b4.y;
        Bs[lc + 2][lr] = b4.z; Bs[lc + 3][lr] = b4.w;
        __syncthreads();

        #pragma unroll
        for (int k = 0; k < BK; k++) {
            float ra[TM], rb[TN];
            #pragma unroll
            for (int i = 0; i < TM; i++) ra[i] = As[k][ty * TM + i];
            #pragma unroll
            for (int j = 0; j < TN; j++) rb[j] = Bs[k][tx * TN + j];
            #pragma unroll
            for (int i = 0; i < TM; i++)
                #pragma unroll
                for (int j = 0; j < TN; j++)
                    acc[i][j] = fmaf(ra[i], rb[j], acc[i][j]);
        }
        __syncthreads();
    }

    #pragma unroll
    for (int i = 0; i < TM; i++) {
        float* crow = C + (size_t)(by * BM + ty * TM + i) * MDIM + bx * BN + tx * TN;
        *(float4*)(crow + 0) = make_float4(acc[i][0], acc[i][1], acc[i][2], acc[i][3]);
        *(float4*)(crow + 4) = make_float4(acc[i][4], acc[i][5], acc[i][6], acc[i][7]);
    }
}

// ---------------------------------------------------------------------------
// Kernel 4: out = fwht(out) * (1/64) * SV, in place, row-wise
// ---------------------------------------------------------------------------
__global__ void k_fwht_out(float* __restrict__ io,
                           const float* __restrict__ SV)
{
    __shared__ float s[MDIM];
    const int row = blockIdx.x;
    float* r = io + (size_t)row * MDIM;
    for (int i = threadIdx.x; i < MDIM; i += 1024)
        s[i] = r[i];
    __syncthreads();
    for (int h = 1; h < MDIM; h <<= 1) {
        for (int p = threadIdx.x; p < MDIM / 2; p += 1024) {
            int i = ((p & ~(h - 1)) << 1) | (p & (h - 1));
            int j = i + h;
            float a = s[i], b = s[j];
            s[i] = a + b;
            s[j] = a - b;
        }
        __syncthreads();
    }
    for (int i = threadIdx.x; i < MDIM; i += 1024)
        r[i] = s[i] * 0.015625f * SV[i];
}

// ---------------------------------------------------------------------------
extern "C" void kernel_launch(void* const* d_in, const int* in_sizes, int n_in,
                              void* d_out, int out_size)
{
    const float* input = (const float*)d_in[0];   // (2,2048,4096) f32
    const float* SU    = (const float*)d_in[1];   // (4096,)
    const float* SV    = (const float*)d_in[2];   // (4096,)
    const float* grid  = (const float*)d_in[3];   // (65536,8)
    const int*   qidx  = (const int*)  d_in[4];   // (4096,512)
    float* out = (float*)d_out;                    // (2,2048,4096) f32

    (void)in_sizes; (void)n_in; (void)out_size;

    k_dequant<<<NIDX / 256, 256>>>(grid, qidx);
    k_fwht_in<<<MROWS, 1024>>>(input, SU);
    {
        dim3 gridDim(MDIM / BN, MROWS / BM);
        k_sgemm_nt<<<gridDim, 256>>>(out);
    }
    k_fwht_out<<<MROWS, 1024>>>(out, SV);
}

// round 3
// speedup vs baseline: 3.5161x; 3.5161x over previous
#include <cuda_runtime.h>
#include <cuda_bf16.h>
#include <cstdint>

#define MROWS 4096
#define NDIM  4096
#define MDIM  4096
#define NIDX  (MDIM * (NDIM / 8))

// ---------------- GEMM tiling ----------------
#define BM 128
#define BN 128
#define BK 32
#define STAGES 3
#define NKCHUNK (NDIM / BK)          // 128

// smem: per stage 4 arrays (Ah, Al, Bh, Bl), each 128 rows x 80B (32 bf16 + 16B pad)
#define ROWB      80
#define ARR_BYTES (128 * ROWB)       // 10240
#define STAGE_BYTES (4 * ARR_BYTES)  // 40960
#define SMEM_TOTAL (STAGES * STAGE_BYTES)   // 122880

// Scratch (allocation-free rule): split bf16 operands
__device__ __nv_bfloat16 g_Xh[(size_t)MROWS * NDIM];
__device__ __nv_bfloat16 g_Xl[(size_t)MROWS * NDIM];
__device__ __nv_bfloat16 g_Wh[(size_t)MDIM * NDIM];
__device__ __nv_bfloat16 g_Wl[(size_t)MDIM * NDIM];

// ---------------- PTX helpers (all legal at PTX target sm_103) ----------------
__device__ __forceinline__ uint32_t smem_u32(const void* p) {
    uint32_t a;
    asm("{ .reg .u64 t; cvta.to.shared.u64 t, %1; cvt.u32.u64 %0, t; }" : "=r"(a) : "l"(p));
    return a;
}
__device__ __forceinline__ void cp_async16(uint32_t dst, const void* src) {
    asm volatile("cp.async.cg.shared.global [%0], [%1], 16;" :: "r"(dst), "l"(src));
}
__device__ __forceinline__ void cp_commit() {
    asm volatile("cp.async.commit_group;" ::: "memory");
}
template<int N> __device__ __forceinline__ void cp_wait() {
    asm volatile("cp.async.wait_group %0;" :: "n"(N) : "memory");
}
__device__ __forceinline__ void ldm_x4(uint32_t* r, uint32_t addr) {
    asm volatile("ldmatrix.sync.aligned.m8n8.x4.shared.b16 {%0,%1,%2,%3}, [%4];"
                 : "=r"(r[0]), "=r"(r[1]), "=r"(r[2]), "=r"(r[3]) : "r"(addr));
}
__device__ __forceinline__ void mma_bf16(float* c, const uint32_t* a, uint32_t b0, uint32_t b1) {
    asm volatile(
        "mma.sync.aligned.m16n8k16.row.col.f32.bf16.bf16.f32 "
        "{%0,%1,%2,%3}, {%4,%5,%6,%7}, {%8,%9}, {%0,%1,%2,%3};"
        : "+f"(c[0]), "+f"(c[1]), "+f"(c[2]), "+f"(c[3])
        : "r"(a[0]), "r"(a[1]), "r"(a[2]), "r"(a[3]), "r"(b0), "r"(b1));
}

// ---------------------------------------------------------------------------
// Kernel 1: dequantize + split W into bf16 hi/lo
// ---------------------------------------------------------------------------
__global__ void k_dequant_split(const float* __restrict__ grid,
                                const int*   __restrict__ qidxs)
{
    int t = blockIdx.x * blockDim.x + threadIdx.x;
    if (t >= NIDX) return;
    int idx = qidxs[t];
    const float4* g = (const float4*)(grid + (size_t)idx * 8);
    float4 a = g[0], b = g[1];
    float v[8] = {a.x, a.y, a.z, a.w, b.x, b.y, b.z, b.w};
    __nv_bfloat16 h[8], l[8];
    #pragma unroll
    for (int j = 0; j < 8; j++) {
        h[j] = __float2bfloat16(v[j]);
        l[j] = __float2bfloat16(v[j] - __bfloat162float(h[j]));
    }
    *(uint4*)(g_Wh + (size_t)t * 8) = *(uint4*)h;
    *(uint4*)(g_Wl + (size_t)t * 8) = *(uint4*)l;
}

// ---------------------------------------------------------------------------
// Kernel 2: X = fwht(input * SU)/64, split into bf16 hi/lo
// ---------------------------------------------------------------------------
__global__ void k_fwht_in_split(const float* __restrict__ in,
                                const float* __restrict__ SU)
{
    __shared__ float s[NDIM];
    const int row = blockIdx.x;
    const float* r = in + (size_t)row * NDIM;
    for (int i = threadIdx.x; i < NDIM; i += 1024)
        s[i] = r[i] * SU[i];
    __syncthreads();
    for (int h = 1; h < NDIM; h <<= 1) {
        for (int p = threadIdx.x; p < NDIM / 2; p += 1024) {
            int i = ((p & ~(h - 1)) << 1) | (p & (h - 1));
            int j = i + h;
            float a = s[i], b = s[j];
            s[i] = a + b;
            s[j] = a - b;
        }
        __syncthreads();
    }
    for (int i = threadIdx.x; i < NDIM; i += 1024) {
        float x = s[i] * 0.015625f;
        __nv_bfloat16 hi = __float2bfloat16(x);
        __nv_bfloat16 lo = __float2bfloat16(x - __bfloat162float(hi));
        g_Xh[(size_t)row * NDIM + i] = hi;
        g_Xl[(size_t)row * NDIM + i] = lo;
    }
}

// ---------------------------------------------------------------------------
// Kernel 3: HMMA split-bf16 GEMM  C[M,N] = X[M,K] * W[N,K]^T
// 128x128 tile, BK=32, 3-stage cp.async pipeline, 8 warps (2M x 4N)
// ---------------------------------------------------------------------------
__device__ __forceinline__ void issue_stage_loads(
    uint32_t sb, int buf, int c, int tid,
    const __nv_bfloat16* Ah, const __nv_bfloat16* Al,
    const __nv_bfloat16* Bh, const __nv_bfloat16* Bl)
{
    const int k0 = c * BK;
    const uint32_t stage = sb + buf * STAGE_BYTES;
    const __nv_bfloat16* gsrc[4] = {Ah, Al, Bh, Bl};
    #pragma unroll
    for (int arr = 0; arr < 4; arr++) {
        const __nv_bfloat16* g = gsrc[arr];
        #pragma unroll
        for (int it = 0; it < 2; it++) {
            int idx = tid + it * 256;       // 0..511
            int r = idx >> 2;               // 0..127
            int cb = idx & 3;               // 16B chunk within row
            uint32_t dst = stage + arr * ARR_BYTES + r * ROWB + cb * 16;
            cp_async16(dst, g + (size_t)r * NDIM + k0 + cb * 8);
        }
    }
}

__global__ __launch_bounds__(256, 1)
void k_gemm_hmma(float* __restrict__ C)
{
    extern __shared__ char smem[];
    const uint32_t sb = smem_u32(smem);
    const int tid = threadIdx.x;
    const int wid = tid >> 5, lane = tid & 31;
    const int wm = wid & 1;          // 0..1 (M)
    const int wn = wid >> 1;         // 0..3 (N)

    const __nv_bfloat16* Ah = g_Xh + (size_t)blockIdx.y * BM * NDIM;
    const __nv_bfloat16* Al = g_Xl + (size_t)blockIdx.y * BM * NDIM;
    const __nv_bfloat16* Bh = g_Wh + (size_t)blockIdx.x * BN * NDIM;
    const __nv_bfloat16* Bl = g_Wl + (size_t)blockIdx.x * BN * NDIM;

    float acc[4][4][4];
    #pragma unroll
    for (int i = 0; i < 4; i++)
        #pragma unroll
        for (int j = 0; j < 4; j++)
            #pragma unroll
            for (int e = 0; e < 4; e++) acc[i][j][e] = 0.f;

    issue_stage_loads(sb, 0, 0, tid, Ah, Al, Bh, Bl); cp_commit();
    issue_stage_loads(sb, 1, 1, tid, Ah, Al, Bh, Bl); cp_commit();

    // per-lane ldmatrix address components
    const int lrow = lane & 15;              // row within 16-row tile
    const int lkb  = (lane >> 4) * 16;       // 0 or 16 bytes (8 bf16)

    int buf = 0;
    for (int c = 0; c < NKCHUNK; c++) {
        cp_wait<1>();
        __syncthreads();

        if (c + 2 < NKCHUNK)
            issue_stage_loads(sb, (buf + 2) % STAGES, c + 2, tid, Ah, Al, Bh, Bl);
        cp_commit();

        const uint32_t stage = sb + buf * STAGE_BYTES;
        const uint32_t sAh = stage;
        const uint32_t sAl = stage + ARR_BYTES;
        const uint32_t sBh = stage + 2 * ARR_BYTES;
        const uint32_t sBl = stage + 3 * ARR_BYTES;

        #pragma unroll
        for (int kk = 0; kk < 2; kk++) {     // two k16 steps per BK=32
            const int kb = kk * 32 + lkb;    // byte offset in row
            uint32_t a_h[4][4], a_l[4][4];
            uint32_t b_h[2][4], b_l[2][4];
            #pragma unroll
            for (int i = 0; i < 4; i++) {
                int row = wm * 64 + i * 16 + lrow;
                ldm_x4(a_h[i], sAh + row * ROWB + kb);
                ldm_x4(a_l[i], sAl + row * ROWB + kb);
            }
            #pragma unroll
            for (int bt = 0; bt < 2; bt++) {
                int nrow = wn * 32 + bt * 16 + lrow;
                ldm_x4(b_h[bt], sBh + nrow * ROWB + kb);
                ldm_x4(b_l[bt], sBl + nrow * ROWB + kb);
            }
            #pragma unroll
            for (int i = 0; i < 4; i++)
                #pragma unroll
                for (int j = 0; j < 4; j++) {
                    const int bt = j >> 1, odd = j & 1;
                    uint32_t bh0 = b_h[bt][odd],     bh1 = b_h[bt][odd + 2];
                    uint32_t bl0 = b_l[bt][odd],     bl1 = b_l[bt][odd + 2];
                    mma_bf16(acc[i][j], a_h[i], bh0, bh1);   // Ah*Bh
                    mma_bf16(acc[i][j], a_h[i], bl0, bl1);   // Ah*Bl
                    mma_bf16(acc[i][j], a_l[i], bh0, bh1);   // Al*Bh
                }
        }
        buf = (buf + 1) % STAGES;
        __syncthreads();
    }

    // Epilogue
    const int crow0 = blockIdx.y * BM + wm * 64 + (lane >> 2);
    const int ccol0 = blockIdx.x * BN + wn * 32 + (lane & 3) * 2;
    #pragma unroll
    for (int i = 0; i < 4; i++)
        #pragma unroll
        for (int j = 0; j < 4; j++) {
            float* p0 = C + (size_t)(crow0 + i * 16)     * MDIM + ccol0 + j * 8;
            float* p1 = C + (size_t)(crow0 + i * 16 + 8) * MDIM + ccol0 + j * 8;
            *(float2*)p0 = make_float2(acc[i][j][0], acc[i][j][1]);
            *(float2*)p1 = make_float2(acc[i][j][2], acc[i][j][3]);
        }
}

// ---------------------------------------------------------------------------
// Kernel 4: out = fwht(out)/64 * SV, in place
// ---------------------------------------------------------------------------
__global__ void k_fwht_out(float* __restrict__ io,
                           const float* __restrict__ SV)
{
    __shared__ float s[MDIM];
    const int row = blockIdx.x;
    float* r = io + (size_t)row * MDIM;
    for (int i = threadIdx.x; i < MDIM; i += 1024)
        s[i] = r[i];
    __syncthreads();
    for (int h = 1; h < MDIM; h <<= 1) {
        for (int p = threadIdx.x; p < MDIM / 2; p += 1024) {
            int i = ((p & ~(h - 1)) << 1) | (p & (h - 1));
            int j = i + h;
            float a = s[i], b = s[j];
            s[i] = a + b;
            s[j] = a - b;
        }
        __syncthreads();
    }
    for (int i = threadIdx.x; i < MDIM; i += 1024)
        r[i] = s[i] * 0.015625f * SV[i];
}

// ---------------------------------------------------------------------------
extern "C" void kernel_launch(void* const* d_in, const int* in_sizes, int n_in,
                              void* d_out, int out_size)
{
    const float* input = (const float*)d_in[0];
    const float* SU    = (const float*)d_in[1];
    const float* SV    = (const float*)d_in[2];
    const float* grid  = (const float*)d_in[3];
    const int*   qidx  = (const int*)  d_in[4];
    float* out = (float*)d_out;
    (void)in_sizes; (void)n_in; (void)out_size;

    cudaFuncSetAttribute(k_gemm_hmma, cudaFuncAttributeMaxDynamicSharedMemorySize, SMEM_TOTAL);

    k_dequant_split<<<NIDX / 256, 256>>>(grid, qidx);
    k_fwht_in_split<<<MROWS, 1024>>>(input, SU);
    {
        dim3 gd(MDIM / BN, MROWS / BM);
        k_gemm_hmma<<<gd, 256, SMEM_TOTAL>>>(out);
    }
    k_fwht_out<<<MROWS, 1024>>>(out, SV);
}